// round 12
// baseline (speedup 1.0000x reference)
#include <cuda_runtime.h>
#include <cuda_bf16.h>
#include <math.h>
#include <stdint.h>

#define BSZ   32
#define NT    196
#define DV    1024
#define NBOX  512
#define GRID_ 14
#define MAXATT 9
#define NLAB  20

#define Y_OFF   0
#define L_OFF   (NBOX * DV)              // 524288
#define D_OFF   (L_OFF + NBOX * MAXATT)  // 528896

#define INV254 (1.0f / 254.0f)

__constant__ int c_id2cat[NLAB] = {3,5,2,4,6,3,7,2,5,4,8,3,2,6,5,4,3,9,2,5};

__device__ __align__(16) uint32_t g_aq1[NBOX * DV / 4];
__device__ __align__(16) uint32_t g_aq2[NBOX * DV / 4];
__device__ __align__(16) uint32_t g_bq1[DV * DV / 4];
__device__ __align__(16) uint32_t g_bq2[DV * DV / 4];
__device__ float g_sa[NBOX];
__device__ float g_sb[DV];
__device__ float g_h[NBOX * DV];

__device__ __forceinline__ float warp_max(float v) {
    v = fmaxf(v, __shfl_xor_sync(0xffffffff, v, 16));
    v = fmaxf(v, __shfl_xor_sync(0xffffffff, v, 8));
    v = fmaxf(v, __shfl_xor_sync(0xffffffff, v, 4));
    v = fmaxf(v, __shfl_xor_sync(0xffffffff, v, 2));
    v = fmaxf(v, __shfl_xor_sync(0xffffffff, v, 1));
    return v;
}

__device__ __forceinline__ int q8(float x, float inv) {
    int q = __float2int_rn(x * inv);
    return max(-127, min(127, q));
}

__device__ __forceinline__ void cpa16(uint32_t dst, const void* src) {
    asm volatile("cp.async.cg.shared.global [%0], [%1], 16;" :: "r"(dst), "l"(src));
}

// ---------------------------------------------------------------------------
// Kernel A: blocks [0,512): ROI max pool via cp.async smem staging (MLP=11),
//           then 2-level int8 quant (per-row scale).
//           blocks [512,1024): W_ff rows -> 2-level int8 quant (2 rows/block)
// ---------------------------------------------------------------------------
#define CHUNK 11

__global__ __launch_bounds__(256) void pre_kernel(
    const float* __restrict__ x, const float* __restrict__ boxes,
    const float* __restrict__ W)
{
    __shared__ __align__(16) float4 cells[CHUNK][256];   // 45056 B
    __shared__ int   cell_off[196];
    __shared__ float smx[8];

    const int tid  = threadIdx.x;
    const int lane = tid & 31;
    const int wrp  = tid >> 5;

    if (blockIdx.x >= NBOX) {
        // ---- W quantize: 2 rows per block, 128 threads per row, 8 floats each
        const int wb    = blockIdx.x - NBOX;
        const int rhalf = tid >> 7;
        const int row_g = wb * 2 + rhalf;
        const int li    = tid & 127;
        const float* wr = W + (size_t)row_g * DV + li * 8;
        float4 v0 = *(const float4*)(wr);
        float4 v1 = *(const float4*)(wr + 4);
        float v[8] = {v0.x, v0.y, v0.z, v0.w, v1.x, v1.y, v1.z, v1.w};

        float am = 0.f;
        #pragma unroll
        for (int i = 0; i < 8; ++i) am = fmaxf(am, fabsf(v[i]));
        am = warp_max(am);
        if (lane == 0) smx[wrp] = am;
        __syncthreads();
        const int b0 = rhalf * 4;
        float rowmax = fmaxf(fmaxf(smx[b0], smx[b0 + 1]),
                             fmaxf(smx[b0 + 2], smx[b0 + 3]));
        float sa   = rowmax > 0.f ? rowmax * (1.f / 127.f) : 1.f;
        float inv1 = 1.f / sa;
        float inv2 = 254.f / sa;

        uint32_t p1[2] = {0, 0}, p2[2] = {0, 0};
        #pragma unroll
        for (int i = 0; i < 8; ++i) {
            int a = q8(v[i], inv1);
            float r = v[i] - (float)a * sa;
            int b = q8(r, inv2);
            p1[i >> 2] |= ((uint32_t)a & 0xFF) << ((i & 3) * 8);
            p2[i >> 2] |= ((uint32_t)b & 0xFF) << ((i & 3) * 8);
        }
        uint32_t* d1 = g_bq1 + ((size_t)row_g * DV + li * 8) / 4;
        uint32_t* d2 = g_bq2 + ((size_t)row_g * DV + li * 8) / 4;
        d1[0] = p1[0]; d1[1] = p1[1];
        d2[0] = p2[0]; d2[1] = p2[1];
        if (li == 0) g_sb[row_g] = sa;
        return;
    }

    // ---- ROI pool ----
    const int n = blockIdx.x;
    const float SC = 14.0f / 224.0f;
    float b0f = boxes[n * 5 + 0];
    float fx1 = boxes[n * 5 + 1];
    float fy1 = boxes[n * 5 + 2];
    float fx2 = boxes[n * 5 + 3];
    float fy2 = boxes[n * 5 + 4];
    int bidx = (int)b0f;
    int cx1 = (int)floorf(fx1 * SC + 0.5f);
    int cy1 = (int)floorf(fy1 * SC + 0.5f);
    int cx2 = (int)floorf(fx2 * SC + 0.5f);
    int cy2 = (int)floorf(fy2 * SC + 0.5f);

    int hs = min(max(cy1, 0), GRID_);
    int he = min(max(max(cy2 + 1, cy1 + 1), 0), GRID_);
    int ws = min(max(cx1, 0), GRID_);
    int we = min(max(max(cx2 + 1, cx1 + 1), 0), GRID_);

    const bool valid = (hs < he) && (ws < we);
    const int ww_ = we - ws;
    const int nc  = valid ? (he - hs) * ww_ : 0;

    // parallel per-cell coordinate computation: ONE division per thread
    if (tid < nc) {
        int hh = tid / ww_;
        int wi = tid - hh * ww_;
        cell_off[tid] = ((hs + hh) * GRID_ + (ws + wi)) * (DV / 4);
    }
    __syncthreads();

    float4 mx = make_float4(0.f, 0.f, 0.f, 0.f);
    if (valid) {
        const float4* xb = (const float4*)(x + (size_t)bidx * NT * DV);
        mx = make_float4(-INFINITY, -INFINITY, -INFINITY, -INFINITY);
        for (int c0 = 0; c0 < nc; c0 += CHUNK) {
            const int cnt = min(CHUNK, nc - c0);
            for (int i = 0; i < cnt; ++i) {
                cpa16((uint32_t)__cvta_generic_to_shared(&cells[i][tid]),
                      xb + cell_off[c0 + i] + tid);
            }
            asm volatile("cp.async.commit_group;");
            asm volatile("cp.async.wait_group 0;");
            __syncthreads();
            for (int i = 0; i < cnt; ++i) {
                float4 v = cells[i][tid];
                mx.x = fmaxf(mx.x, v.x);
                mx.y = fmaxf(mx.y, v.y);
                mx.z = fmaxf(mx.z, v.z);
                mx.w = fmaxf(mx.w, v.w);
            }
            __syncthreads();
        }
    }

    // 2-level int8 quantization (per-row scale)
    float v[4] = {mx.x, mx.y, mx.z, mx.w};
    float am = fmaxf(fmaxf(fabsf(v[0]), fabsf(v[1])),
                     fmaxf(fabsf(v[2]), fabsf(v[3])));
    am = warp_max(am);
    if (lane == 0) smx[wrp] = am;
    __syncthreads();
    float rowmax = 0.f;
    #pragma unroll
    for (int i = 0; i < 8; ++i) rowmax = fmaxf(rowmax, smx[i]);
    float sa   = rowmax > 0.f ? rowmax * (1.f / 127.f) : 1.f;
    float inv1 = 1.f / sa;
    float inv2 = 254.f / sa;

    uint32_t p1 = 0, p2 = 0;
    #pragma unroll
    for (int i = 0; i < 4; ++i) {
        int a = q8(v[i], inv1);
        float r = v[i] - (float)a * sa;
        int b = q8(r, inv2);
        p1 |= ((uint32_t)a & 0xFF) << (i * 8);
        p2 |= ((uint32_t)b & 0xFF) << (i * 8);
    }
    g_aq1[((size_t)n * DV) / 4 + tid] = p1;
    g_aq2[((size_t)n * DV) / 4 + tid] = p2;
    if (tid == 0) g_sa[n] = sa;
}

// ---------------------------------------------------------------------------
// Kernel B: h = pooled @ W^T + bias via int8 mma m16n8k32, 3-term split:
//   C1 = q1a*q1b, C2 = q2a*q1b, C3 = q1a*q2b (exact s32 accum)
//   h  = sa*sb*(C1 + (C2+C3)/254) + bias
// 64x64 tiles, K=64 per stage (two k32 sub-steps per sync), 256 threads,
// cp.async double buffer. smem rows stride 80B (16x5: ldmatrix conflict-free).
// ---------------------------------------------------------------------------
__device__ __forceinline__ void ldsm4(uint32_t r[4], uint32_t addr) {
    asm volatile("ldmatrix.sync.aligned.m8n8.x4.shared.b16 {%0,%1,%2,%3}, [%4];"
                 : "=r"(r[0]), "=r"(r[1]), "=r"(r[2]), "=r"(r[3]) : "r"(addr));
}

__device__ __forceinline__ void mma_s8(int c[4], const uint32_t a[4],
                                       uint32_t b0, uint32_t b1) {
    asm volatile(
        "mma.sync.aligned.m16n8k32.row.col.s32.s8.s8.s32 "
        "{%0,%1,%2,%3}, {%4,%5,%6,%7}, {%8,%9}, {%0,%1,%2,%3};\n"
        : "+r"(c[0]), "+r"(c[1]), "+r"(c[2]), "+r"(c[3])
        : "r"(a[0]), "r"(a[1]), "r"(a[2]), "r"(a[3]), "r"(b0), "r"(b1));
}

__global__ __launch_bounds__(256) void gemm_s8_kernel(const float* __restrict__ bias)
{
    // S[stage][arr 0=Aq1,1=Aq2,2=Bq1,3=Bq2][row 0..63][80 bytes (64 data)]
    __shared__ __align__(16) int8_t S[2][4][64][80];

    const int tid  = threadIdx.x;
    const int lane = tid & 31;
    const int wid  = tid >> 5;
    const int wm   = (wid & 1) * 32;
    const int wn   = (wid >> 1) * 16;
    const int bm64 = blockIdx.y * 64;
    const int bn64 = blockIdx.x * 64;

    // load split: 256 threads x 64B (4 x cpa16) per stage
    const int arr_a = tid >> 7;           // 0 -> q1 arrays, 1 -> q2 arrays
    const int rowi  = (tid & 127) >> 1;   // 0..63
    const int off0  = (tid & 1) << 5;     // 0 or 32
    const int8_t* srcA = (const int8_t*)(arr_a ? g_aq2 : g_aq1)
                       + (size_t)(bm64 + rowi) * DV + off0;
    const int8_t* srcB = (const int8_t*)(arr_a ? g_bq2 : g_bq1)
                       + (size_t)(bn64 + rowi) * DV + off0;

    #define ISSUE(ST, K0)                                                       \
    {                                                                           \
        cpa16((uint32_t)__cvta_generic_to_shared(&S[ST][arr_a][rowi][off0]),    \
              srcA + (K0));                                                     \
        cpa16((uint32_t)__cvta_generic_to_shared(&S[ST][arr_a][rowi][off0+16]), \
              srcA + (K0) + 16);                                                \
        cpa16((uint32_t)__cvta_generic_to_shared(&S[ST][2+arr_a][rowi][off0]),  \
              srcB + (K0));                                                     \
        cpa16((uint32_t)__cvta_generic_to_shared(&S[ST][2+arr_a][rowi][off0+16]),\
              srcB + (K0) + 16);                                                \
    }

    const int arow = lane & 15;
    const int aoff = (lane >> 4) * 16;
    const int brow = (lane & 7) + ((lane >> 4) << 3);
    const int boff = ((lane >> 3) & 1) * 16;

    int c1[2][2][4] = {}, c2[2][2][4] = {}, c3[2][2][4] = {};

    ISSUE(0, 0);
    asm volatile("cp.async.commit_group;");
    ISSUE(1, 64);
    asm volatile("cp.async.commit_group;");

    for (int it = 0; it < DV / 64; ++it) {
        const int s = it & 1;
        asm volatile("cp.async.wait_group 1;");
        __syncthreads();

        #pragma unroll
        for (int kc = 0; kc < 64; kc += 32) {
            uint32_t a1[2][4], a2[2][4], b1[4], b2[4];
            #pragma unroll
            for (int ms = 0; ms < 2; ++ms) {
                ldsm4(a1[ms], (uint32_t)__cvta_generic_to_shared(
                          &S[s][0][wm + ms * 16 + arow][kc + aoff]));
                ldsm4(a2[ms], (uint32_t)__cvta_generic_to_shared(
                          &S[s][1][wm + ms * 16 + arow][kc + aoff]));
            }
            ldsm4(b1, (uint32_t)__cvta_generic_to_shared(
                      &S[s][2][wn + brow][kc + boff]));
            ldsm4(b2, (uint32_t)__cvta_generic_to_shared(
                      &S[s][3][wn + brow][kc + boff]));

            #pragma unroll
            for (int ms = 0; ms < 2; ++ms) {
                #pragma unroll
                for (int nn = 0; nn < 2; ++nn) {
                    mma_s8(c1[ms][nn], a1[ms], b1[nn * 2], b1[nn * 2 + 1]);
                    mma_s8(c2[ms][nn], a2[ms], b1[nn * 2], b1[nn * 2 + 1]);
                    mma_s8(c3[ms][nn], a1[ms], b2[nn * 2], b2[nn * 2 + 1]);
                }
            }
        }

        __syncthreads();
        if (it + 2 < DV / 64) { ISSUE(s, (it + 2) * 64); }
        asm volatile("cp.async.commit_group;");
    }
    #undef ISSUE

    const int g   = lane >> 2;
    const int tig = lane & 3;
    #pragma unroll
    for (int ms = 0; ms < 2; ++ms) {
        const int m0 = bm64 + wm + ms * 16 + g;
        const float sA0 = g_sa[m0];
        const float sA1 = g_sa[m0 + 8];
        #pragma unroll
        for (int nn = 0; nn < 2; ++nn) {
            const int n0 = bn64 + wn + nn * 8 + tig * 2;
            const float sB0 = g_sb[n0];
            const float sB1 = g_sb[n0 + 1];
            float2 bv = *(const float2*)(bias + n0);
            float t0 = (float)c1[ms][nn][0] +
                       ((float)c2[ms][nn][0] + (float)c3[ms][nn][0]) * INV254;
            float t1 = (float)c1[ms][nn][1] +
                       ((float)c2[ms][nn][1] + (float)c3[ms][nn][1]) * INV254;
            float t2 = (float)c1[ms][nn][2] +
                       ((float)c2[ms][nn][2] + (float)c3[ms][nn][2]) * INV254;
            float t3 = (float)c1[ms][nn][3] +
                       ((float)c2[ms][nn][3] + (float)c3[ms][nn][3]) * INV254;
            float2 r0, r1;
            r0.x = sA0 * sB0 * t0 + bv.x;
            r0.y = sA0 * sB1 * t1 + bv.y;
            r1.x = sA1 * sB0 * t2 + bv.x;
            r1.y = sA1 * sB1 * t3 + bv.y;
            *(float2*)(g_h + (size_t)m0 * DV + n0)       = r0;
            *(float2*)(g_h + (size_t)(m0 + 8) * DV + n0) = r1;
        }
    }
}

// ---------------------------------------------------------------------------
// Kernel C: LayerNorm + exact GELU + heads. One block (256 thr) per box row.
// ---------------------------------------------------------------------------
__device__ __forceinline__ float warp_sum(float v) {
    v += __shfl_xor_sync(0xffffffff, v, 16);
    v += __shfl_xor_sync(0xffffffff, v, 8);
    v += __shfl_xor_sync(0xffffffff, v, 4);
    v += __shfl_xor_sync(0xffffffff, v, 2);
    v += __shfl_xor_sync(0xffffffff, v, 1);
    return v;
}

__global__ __launch_bounds__(256) void epilogue_kernel(
    const float* __restrict__ ln_g, const float* __restrict__ ln_b,
    const int*   __restrict__ labels,
    const float* __restrict__ Wh, const float* __restrict__ bh,
    const float* __restrict__ Wd, const float* __restrict__ bd,
    float* __restrict__ out)
{
    __shared__ float sred[8];
    __shared__ float red10[10][8];

    const int r    = blockIdx.x;
    const int tid  = threadIdx.x;
    const int lane = tid & 31;
    const int wid  = tid >> 5;
    const int d    = tid * 4;

    float4 hv = *(const float4*)(g_h + (size_t)r * DV + d);

    float s = warp_sum(hv.x + hv.y + hv.z + hv.w);
    if (lane == 0) sred[wid] = s;
    __syncthreads();
    float tot = 0.f;
    #pragma unroll
    for (int i = 0; i < 8; ++i) tot += sred[i];
    const float mu = tot * (1.0f / DV);
    __syncthreads();

    float cx = hv.x - mu, cy = hv.y - mu, cz = hv.z - mu, cw = hv.w - mu;
    float s2 = warp_sum(cx * cx + cy * cy + cz * cz + cw * cw);
    if (lane == 0) sred[wid] = s2;
    __syncthreads();
    float tot2 = 0.f;
    #pragma unroll
    for (int i = 0; i < 8; ++i) tot2 += sred[i];
    const float rstd = rsqrtf(tot2 * (1.0f / DV) + 1e-5f);

    float4 g4 = *(const float4*)(ln_g + d);
    float4 b4 = *(const float4*)(ln_b + d);
    float4 y4;
    y4.x = cx * rstd * g4.x + b4.x;
    y4.y = cy * rstd * g4.y + b4.y;
    y4.z = cz * rstd * g4.z + b4.z;
    y4.w = cw * rstd * g4.w + b4.w;

    const float IS2 = 0.70710678118654752f;
    y4.x = y4.x * 0.5f * (1.0f + erff(y4.x * IS2));
    y4.y = y4.y * 0.5f * (1.0f + erff(y4.y * IS2));
    y4.z = y4.z * 0.5f * (1.0f + erff(y4.z * IS2));
    y4.w = y4.w * 0.5f * (1.0f + erff(y4.w * IS2));

    *(float4*)(out + Y_OFF + (size_t)r * DV + d) = y4;

    const int lab  = labels[r];
    const int ncat = c_id2cat[lab];
    const float* whp = Wh + (size_t)lab * MAXATT * DV;

    float p[10];
    #pragma unroll
    for (int k = 0; k < MAXATT; ++k) {
        if (k < ncat) {
            float4 w4 = *(const float4*)(whp + (size_t)k * DV + d);
            p[k] = y4.x * w4.x + y4.y * w4.y + y4.z * w4.z + y4.w * w4.w;
        } else {
            p[k] = 0.0f;
        }
    }
    {
        float4 w4 = *(const float4*)(Wd + d);
        p[9] = y4.x * w4.x + y4.y * w4.y + y4.z * w4.z + y4.w * w4.w;
    }

    __syncthreads();
    #pragma unroll
    for (int i = 0; i < 10; ++i) {
        float v = warp_sum(p[i]);
        if (lane == 0) red10[i][wid] = v;
    }
    __syncthreads();

    if (tid < 10) {
        float t2 = 0.f;
        #pragma unroll
        for (int i = 0; i < 8; ++i) t2 += red10[tid][i];
        if (tid < MAXATT) {
            float lv = (tid < ncat) ? (t2 + bh[lab * MAXATT + tid]) : 0.0f;
            out[L_OFF + r * MAXATT + tid] = lv;
        } else {
            out[D_OFF + r] = t2 + bd[0];
        }
    }
}

// ---------------------------------------------------------------------------
extern "C" void kernel_launch(void* const* d_in, const int* in_sizes, int n_in,
                              void* d_out, int out_size)
{
    const float* x      = (const float*)d_in[0];
    const float* boxes  = (const float*)d_in[1];
    const int*   labels = (const int*)  d_in[2];
    const float* W_ff   = (const float*)d_in[3];
    const float* b_ff   = (const float*)d_in[4];
    const float* ln_g   = (const float*)d_in[5];
    const float* ln_b   = (const float*)d_in[6];
    const float* Wh     = (const float*)d_in[7];
    const float* bh     = (const float*)d_in[8];
    const float* Wd     = (const float*)d_in[9];
    const float* bd     = (const float*)d_in[10];
    float* out = (float*)d_out;

    pre_kernel<<<NBOX + 512, 256>>>(x, boxes, W_ff);

    dim3 gg(DV / 64, NBOX / 64);   // 16 x 8 = 128 blocks
    gemm_s8_kernel<<<gg, 256>>>(b_ff);

    epilogue_kernel<<<NBOX, 256>>>(ln_g, ln_b, labels, Wh, bh, Wd, bd, out);
}

// round 15
// speedup vs baseline: 1.0543x; 1.0543x over previous
#include <cuda_runtime.h>
#include <cuda_bf16.h>
#include <math.h>
#include <stdint.h>

#define BSZ   32
#define NT    196
#define DV    1024
#define NBOX  512
#define GRID_ 14
#define MAXATT 9
#define NLAB  20

#define Y_OFF   0
#define L_OFF   (NBOX * DV)              // 524288
#define D_OFF   (L_OFF + NBOX * MAXATT)  // 528896

#define INV254 (1.0f / 254.0f)

__constant__ int c_id2cat[NLAB] = {3,5,2,4,6,3,7,2,5,4,8,3,2,6,5,4,3,9,2,5};

// A and B both 2-level int8 (q1 + q2/254), per-row scales.
__device__ __align__(16) uint32_t g_aq1[NBOX * DV / 4];
__device__ __align__(16) uint32_t g_aq2[NBOX * DV / 4];
__device__ __align__(16) uint32_t g_bq1[DV * DV / 4];
__device__ __align__(16) uint32_t g_bq2[DV * DV / 4];
__device__ float g_sa[NBOX];
__device__ float g_sb[DV];
__device__ float g_h[NBOX * DV];

__device__ __forceinline__ float warp_max(float v) {
    v = fmaxf(v, __shfl_xor_sync(0xffffffff, v, 16));
    v = fmaxf(v, __shfl_xor_sync(0xffffffff, v, 8));
    v = fmaxf(v, __shfl_xor_sync(0xffffffff, v, 4));
    v = fmaxf(v, __shfl_xor_sync(0xffffffff, v, 2));
    v = fmaxf(v, __shfl_xor_sync(0xffffffff, v, 1));
    return v;
}

__device__ __forceinline__ int q8(float x, float inv) {
    int q = __float2int_rn(x * inv);
    return max(-127, min(127, q));
}

__device__ __forceinline__ void cpa16(uint32_t dst, const void* src) {
    asm volatile("cp.async.cg.shared.global [%0], [%1], 16;" :: "r"(dst), "l"(src));
}

// ---------------------------------------------------------------------------
// Kernel A (512 threads/block):
//   blocks [0,256):   ROI max pool, 2 boxes per block (256-thr groups),
//                     then 2-level int8 quant (per-row scale).
//   blocks [256,512): W_ff -> 2-level int8 quant, 4 rows per block.
// Tail-pairing: two boxes share a block so long/short boxes average out.
// ---------------------------------------------------------------------------
__global__ __launch_bounds__(512) void pre_kernel(
    const float* __restrict__ x, const float* __restrict__ boxes,
    const float* __restrict__ W)
{
    __shared__ float smx[16];
    const int tid  = threadIdx.x;
    const int lane = tid & 31;
    const int wrp  = tid >> 5;           // 0..15

    if (blockIdx.x >= 256) {
        // ---- W quantize (2-level): 4 rows per block, 128 threads per row
        const int wb  = blockIdx.x - 256;    // 0..255
        const int rq  = tid >> 7;            // 0..3
        const int row_g = wb * 4 + rq;       // 0..1023
        const int li  = tid & 127;
        const float* wr = W + (size_t)row_g * DV + li * 8;
        float4 v0 = *(const float4*)(wr);
        float4 v1 = *(const float4*)(wr + 4);
        float v[8] = {v0.x, v0.y, v0.z, v0.w, v1.x, v1.y, v1.z, v1.w};

        float am = 0.f;
        #pragma unroll
        for (int i = 0; i < 8; ++i) am = fmaxf(am, fabsf(v[i]));
        am = warp_max(am);
        if (lane == 0) smx[wrp] = am;
        __syncthreads();
        const int b0 = rq * 4;
        float rowmax = fmaxf(fmaxf(smx[b0], smx[b0 + 1]),
                             fmaxf(smx[b0 + 2], smx[b0 + 3]));
        float sa   = rowmax > 0.f ? rowmax * (1.f / 127.f) : 1.f;
        float inv1 = 1.f / sa;
        float inv2 = 254.f / sa;

        uint32_t p1[2] = {0, 0}, p2[2] = {0, 0};
        #pragma unroll
        for (int i = 0; i < 8; ++i) {
            int a = q8(v[i], inv1);
            float r = v[i] - (float)a * sa;
            int b = q8(r, inv2);
            p1[i >> 2] |= ((uint32_t)a & 0xFF) << ((i & 3) * 8);
            p2[i >> 2] |= ((uint32_t)b & 0xFF) << ((i & 3) * 8);
        }
        uint32_t* d1 = g_bq1 + ((size_t)row_g * DV + li * 8) / 4;
        uint32_t* d2 = g_bq2 + ((size_t)row_g * DV + li * 8) / 4;
        d1[0] = p1[0]; d1[1] = p1[1];
        d2[0] = p2[0]; d2[1] = p2[1];
        if (li == 0) g_sb[row_g] = sa;
        return;
    }

    // ---- ROI pool: group g handles box n = 2*blockIdx.x + g ----
    const int g    = tid >> 8;            // 0 or 1
    const int t256 = tid & 255;
    const int n    = blockIdx.x * 2 + g;

    const float SC = 14.0f / 224.0f;
    float b0f = boxes[n * 5 + 0];
    float fx1 = boxes[n * 5 + 1];
    float fy1 = boxes[n * 5 + 2];
    float fx2 = boxes[n * 5 + 3];
    float fy2 = boxes[n * 5 + 4];
    int bidx = (int)b0f;
    int cx1 = (int)floorf(fx1 * SC + 0.5f);
    int cy1 = (int)floorf(fy1 * SC + 0.5f);
    int cx2 = (int)floorf(fx2 * SC + 0.5f);
    int cy2 = (int)floorf(fy2 * SC + 0.5f);

    int hs = min(max(cy1, 0), GRID_);
    int he = min(max(max(cy2 + 1, cy1 + 1), 0), GRID_);
    int ws = min(max(cx1, 0), GRID_);
    int we = min(max(max(cx2 + 1, cx1 + 1), 0), GRID_);

    float4 mx = make_float4(0.f, 0.f, 0.f, 0.f);
    if (hs < he && ws < we) {
        const float4* xb = (const float4*)(x + (size_t)bidx * NT * DV);
        mx = make_float4(-INFINITY, -INFINITY, -INFINITY, -INFINITY);
        for (int h = hs; h < he; h += 2) {
            int h1 = min(h + 1, he - 1);
            const float4* r0 = xb + (h  * GRID_) * (DV / 4) + t256;
            const float4* r1 = xb + (h1 * GRID_) * (DV / 4) + t256;
            for (int w = ws; w < we; w += 2) {
                int w1 = min(w + 1, we - 1);
                float4 a = r0[w  * (DV / 4)];
                float4 b = r0[w1 * (DV / 4)];
                float4 c = r1[w  * (DV / 4)];
                float4 d = r1[w1 * (DV / 4)];
                mx.x = fmaxf(fmaxf(fmaxf(mx.x, a.x), fmaxf(b.x, c.x)), d.x);
                mx.y = fmaxf(fmaxf(fmaxf(mx.y, a.y), fmaxf(b.y, c.y)), d.y);
                mx.z = fmaxf(fmaxf(fmaxf(mx.z, a.z), fmaxf(b.z, c.z)), d.z);
                mx.w = fmaxf(fmaxf(fmaxf(mx.w, a.w), fmaxf(b.w, c.w)), d.w);
            }
        }
    }

    float v[4] = {mx.x, mx.y, mx.z, mx.w};
    float am = fmaxf(fmaxf(fabsf(v[0]), fabsf(v[1])),
                     fmaxf(fabsf(v[2]), fabsf(v[3])));
    am = warp_max(am);
    if (lane == 0) smx[wrp] = am;
    __syncthreads();
    float rowmax = 0.f;
    #pragma unroll
    for (int i = 0; i < 8; ++i) rowmax = fmaxf(rowmax, smx[g * 8 + i]);
    float sa   = rowmax > 0.f ? rowmax * (1.f / 127.f) : 1.f;
    float inv1 = 1.f / sa;
    float inv2 = 254.f / sa;

    uint32_t p1 = 0, p2 = 0;
    #pragma unroll
    for (int i = 0; i < 4; ++i) {
        int a = q8(v[i], inv1);
        float r = v[i] - (float)a * sa;
        int b = q8(r, inv2);
        p1 |= ((uint32_t)a & 0xFF) << (i * 8);
        p2 |= ((uint32_t)b & 0xFF) << (i * 8);
    }
    g_aq1[((size_t)n * DV) / 4 + t256] = p1;
    g_aq2[((size_t)n * DV) / 4 + t256] = p2;
    if (t256 == 0) g_sa[n] = sa;
}

// ---------------------------------------------------------------------------
// Kernel B: h = pooled @ W^T + bias via int8 mma m16n8k32, 3-term split:
//   C1 = q1a*q1b, C2 = q2a*q1b, C3 = q1a*q2b (exact s32 accum)
//   h  = sa*sb*(C1 + (C2+C3)/254) + bias
// 64x64x32 tiles, 256 threads (8 warps, 32x16 warp tiles), cp.async dbl buf.
// smem rows stride 48B. (R10 measured-best structure, verbatim.)
// ---------------------------------------------------------------------------
__device__ __forceinline__ void ldsm4(uint32_t r[4], uint32_t addr) {
    asm volatile("ldmatrix.sync.aligned.m8n8.x4.shared.b16 {%0,%1,%2,%3}, [%4];"
                 : "=r"(r[0]), "=r"(r[1]), "=r"(r[2]), "=r"(r[3]) : "r"(addr));
}

__device__ __forceinline__ void mma_s8(int c[4], const uint32_t a[4],
                                       uint32_t b0, uint32_t b1) {
    asm volatile(
        "mma.sync.aligned.m16n8k32.row.col.s32.s8.s8.s32 "
        "{%0,%1,%2,%3}, {%4,%5,%6,%7}, {%8,%9}, {%0,%1,%2,%3};\n"
        : "+r"(c[0]), "+r"(c[1]), "+r"(c[2]), "+r"(c[3])
        : "r"(a[0]), "r"(a[1]), "r"(a[2]), "r"(a[3]), "r"(b0), "r"(b1));
}

__global__ __launch_bounds__(256) void gemm_s8_kernel(const float* __restrict__ bias)
{
    // S[stage][arr 0=Aq1,1=Aq2,2=Bq1,3=Bq2][row 0..63][48 bytes]
    __shared__ __align__(16) int8_t S[2][4][64][48];

    const int tid  = threadIdx.x;
    const int lane = tid & 31;
    const int wid  = tid >> 5;
    const int wm   = (wid & 1) * 32;
    const int wn   = (wid >> 1) * 16;
    const int bm64 = blockIdx.y * 64;
    const int bn64 = blockIdx.x * 64;

    // cp.async task split: each thread loads one A-array chunk + one B-array chunk
    const int arr_a = tid >> 7;           // 0 -> q1 arrays, 1 -> q2 arrays
    const int rowi  = (tid & 127) >> 1;   // 0..63
    const int offi  = (tid & 1) << 4;     // 0 or 16
    const int8_t* srcA = (const int8_t*)(arr_a ? g_aq2 : g_aq1)
                       + (size_t)(bm64 + rowi) * DV + offi;
    const int8_t* srcB = (const int8_t*)(arr_a ? g_bq2 : g_bq1)
                       + (size_t)(bn64 + rowi) * DV + offi;

    #define ISSUE(ST, K0)                                                      \
    {                                                                          \
        cpa16((uint32_t)__cvta_generic_to_shared(&S[ST][arr_a][rowi][offi]),   \
              srcA + (K0));                                                    \
        cpa16((uint32_t)__cvta_generic_to_shared(&S[ST][2 + arr_a][rowi][offi]),\
              srcB + (K0));                                                    \
    }

    const int arow = lane & 15;
    const int aoff = (lane >> 4) * 16;
    const int brow = (lane & 7) + ((lane >> 4) << 3);
    const int boff = ((lane >> 3) & 1) * 16;

    int c1[2][2][4] = {}, c2[2][2][4] = {}, c3[2][2][4] = {};

    ISSUE(0, 0);
    asm volatile("cp.async.commit_group;");
    ISSUE(1, 32);
    asm volatile("cp.async.commit_group;");

    for (int it = 0; it < DV / 32; ++it) {
        const int s = it & 1;
        asm volatile("cp.async.wait_group 1;");
        __syncthreads();

        uint32_t a1[2][4], a2[2][4], b1[4], b2[4];
        #pragma unroll
        for (int ms = 0; ms < 2; ++ms) {
            ldsm4(a1[ms], (uint32_t)__cvta_generic_to_shared(
                      &S[s][0][wm + ms * 16 + arow][aoff]));
            ldsm4(a2[ms], (uint32_t)__cvta_generic_to_shared(
                      &S[s][1][wm + ms * 16 + arow][aoff]));
        }
        ldsm4(b1, (uint32_t)__cvta_generic_to_shared(&S[s][2][wn + brow][boff]));
        ldsm4(b2, (uint32_t)__cvta_generic_to_shared(&S[s][3][wn + brow][boff]));

        #pragma unroll
        for (int ms = 0; ms < 2; ++ms) {
            #pragma unroll
            for (int nn = 0; nn < 2; ++nn) {
                mma_s8(c1[ms][nn], a1[ms], b1[nn * 2], b1[nn * 2 + 1]);
                mma_s8(c2[ms][nn], a2[ms], b1[nn * 2], b1[nn * 2 + 1]);
                mma_s8(c3[ms][nn], a1[ms], b2[nn * 2], b2[nn * 2 + 1]);
            }
        }

        __syncthreads();
        if (it + 2 < DV / 32) { ISSUE(s, (it + 2) * 32); }
        asm volatile("cp.async.commit_group;");
    }
    #undef ISSUE

    const int g   = lane >> 2;
    const int tig = lane & 3;
    #pragma unroll
    for (int ms = 0; ms < 2; ++ms) {
        const int m0 = bm64 + wm + ms * 16 + g;
        const float sA0 = g_sa[m0];
        const float sA1 = g_sa[m0 + 8];
        #pragma unroll
        for (int nn = 0; nn < 2; ++nn) {
            const int n0 = bn64 + wn + nn * 8 + tig * 2;
            const float sB0 = g_sb[n0];
            const float sB1 = g_sb[n0 + 1];
            float2 bv = *(const float2*)(bias + n0);
            float t0 = (float)c1[ms][nn][0] +
                       ((float)c2[ms][nn][0] + (float)c3[ms][nn][0]) * INV254;
            float t1 = (float)c1[ms][nn][1] +
                       ((float)c2[ms][nn][1] + (float)c3[ms][nn][1]) * INV254;
            float t2 = (float)c1[ms][nn][2] +
                       ((float)c2[ms][nn][2] + (float)c3[ms][nn][2]) * INV254;
            float t3 = (float)c1[ms][nn][3] +
                       ((float)c2[ms][nn][3] + (float)c3[ms][nn][3]) * INV254;
            float2 r0, r1;
            r0.x = sA0 * sB0 * t0 + bv.x;
            r0.y = sA0 * sB1 * t1 + bv.y;
            r1.x = sA1 * sB0 * t2 + bv.x;
            r1.y = sA1 * sB1 * t3 + bv.y;
            *(float2*)(g_h + (size_t)m0 * DV + n0)       = r0;
            *(float2*)(g_h + (size_t)(m0 + 8) * DV + n0) = r1;
        }
    }
}

// ---------------------------------------------------------------------------
// Kernel C: LayerNorm + exact GELU + heads. One block (256 thr) per box row.
// ---------------------------------------------------------------------------
__device__ __forceinline__ float warp_sum(float v) {
    v += __shfl_xor_sync(0xffffffff, v, 16);
    v += __shfl_xor_sync(0xffffffff, v, 8);
    v += __shfl_xor_sync(0xffffffff, v, 4);
    v += __shfl_xor_sync(0xffffffff, v, 2);
    v += __shfl_xor_sync(0xffffffff, v, 1);
    return v;
}

__global__ __launch_bounds__(256) void epilogue_kernel(
    const float* __restrict__ ln_g, const float* __restrict__ ln_b,
    const int*   __restrict__ labels,
    const float* __restrict__ Wh, const float* __restrict__ bh,
    const float* __restrict__ Wd, const float* __restrict__ bd,
    float* __restrict__ out)
{
    __shared__ float sred[8];
    __shared__ float red10[10][8];

    const int r    = blockIdx.x;
    const int tid  = threadIdx.x;
    const int lane = tid & 31;
    const int wid  = tid >> 5;
    const int d    = tid * 4;

    float4 hv = *(const float4*)(g_h + (size_t)r * DV + d);

    float s = warp_sum(hv.x + hv.y + hv.z + hv.w);
    if (lane == 0) sred[wid] = s;
    __syncthreads();
    float tot = 0.f;
    #pragma unroll
    for (int i = 0; i < 8; ++i) tot += sred[i];
    const float mu = tot * (1.0f / DV);
    __syncthreads();

    float cx = hv.x - mu, cy = hv.y - mu, cz = hv.z - mu, cw = hv.w - mu;
    float s2 = warp_sum(cx * cx + cy * cy + cz * cz + cw * cw);
    if (lane == 0) sred[wid] = s2;
    __syncthreads();
    float tot2 = 0.f;
    #pragma unroll
    for (int i = 0; i < 8; ++i) tot2 += sred[i];
    const float rstd = rsqrtf(tot2 * (1.0f / DV) + 1e-5f);

    float4 g4 = *(const float4*)(ln_g + d);
    float4 b4 = *(const float4*)(ln_b + d);
    float4 y4;
    y4.x = cx * rstd * g4.x + b4.x;
    y4.y = cy * rstd * g4.y + b4.y;
    y4.z = cz * rstd * g4.z + b4.z;
    y4.w = cw * rstd * g4.w + b4.w;

    const float IS2 = 0.70710678118654752f;
    y4.x = y4.x * 0.5f * (1.0f + erff(y4.x * IS2));
    y4.y = y4.y * 0.5f * (1.0f + erff(y4.y * IS2));
    y4.z = y4.z * 0.5f * (1.0f + erff(y4.z * IS2));
    y4.w = y4.w * 0.5f * (1.0f + erff(y4.w * IS2));

    *(float4*)(out + Y_OFF + (size_t)r * DV + d) = y4;

    const int lab  = labels[r];
    const int ncat = c_id2cat[lab];
    const float* whp = Wh + (size_t)lab * MAXATT * DV;

    float p[10];
    #pragma unroll
    for (int k = 0; k < MAXATT; ++k) {
        if (k < ncat) {
            float4 w4 = *(const float4*)(whp + (size_t)k * DV + d);
            p[k] = y4.x * w4.x + y4.y * w4.y + y4.z * w4.z + y4.w * w4.w;
        } else {
            p[k] = 0.0f;
        }
    }
    {
        float4 w4 = *(const float4*)(Wd + d);
        p[9] = y4.x * w4.x + y4.y * w4.y + y4.z * w4.z + y4.w * w4.w;
    }

    __syncthreads();
    #pragma unroll
    for (int i = 0; i < 10; ++i) {
        float v = warp_sum(p[i]);
        if (lane == 0) red10[i][wid] = v;
    }
    __syncthreads();

    if (tid < 10) {
        float t2 = 0.f;
        #pragma unroll
        for (int i = 0; i < 8; ++i) t2 += red10[tid][i];
        if (tid < MAXATT) {
            float lv = (tid < ncat) ? (t2 + bh[lab * MAXATT + tid]) : 0.0f;
            out[L_OFF + r * MAXATT + tid] = lv;
        } else {
            out[D_OFF + r] = t2 + bd[0];
        }
    }
}

// ---------------------------------------------------------------------------
extern "C" void kernel_launch(void* const* d_in, const int* in_sizes, int n_in,
                              void* d_out, int out_size)
{
    const float* x      = (const float*)d_in[0];
    const float* boxes  = (const float*)d_in[1];
    const int*   labels = (const int*)  d_in[2];
    const float* W_ff   = (const float*)d_in[3];
    const float* b_ff   = (const float*)d_in[4];
    const float* ln_g   = (const float*)d_in[5];
    const float* ln_b   = (const float*)d_in[6];
    const float* Wh     = (const float*)d_in[7];
    const float* bh     = (const float*)d_in[8];
    const float* Wd     = (const float*)d_in[9];
    const float* bd     = (const float*)d_in[10];
    float* out = (float*)d_out;

    pre_kernel<<<512, 512>>>(x, boxes, W_ff);

    dim3 gg(DV / 64, NBOX / 64);   // 16 x 8 = 128 blocks
    gemm_s8_kernel<<<gg, 256>>>(b_ff);

    epilogue_kernel<<<NBOX, 256>>>(ln_g, ln_b, labels, Wh, bh, Wd, bd, out);
}

// round 16
// speedup vs baseline: 1.0831x; 1.0273x over previous
#include <cuda_runtime.h>
#include <cuda_bf16.h>
#include <math.h>
#include <stdint.h>

#define BSZ   32
#define NT    196
#define DV    1024
#define NBOX  512
#define GRID_ 14
#define MAXATT 9
#define NLAB  20

#define Y_OFF   0
#define L_OFF   (NBOX * DV)              // 524288
#define D_OFF   (L_OFF + NBOX * MAXATT)  // 528896

#define INV254 (1.0f / 254.0f)

__constant__ int c_id2cat[NLAB] = {3,5,2,4,6,3,7,2,5,4,8,3,2,6,5,4,3,9,2,5};

// A and B both 2-level int8 (q1 + q2/254), per-row scales.
__device__ __align__(16) uint32_t g_aq1[NBOX * DV / 4];
__device__ __align__(16) uint32_t g_aq2[NBOX * DV / 4];
__device__ __align__(16) uint32_t g_bq1[DV * DV / 4];
__device__ __align__(16) uint32_t g_bq2[DV * DV / 4];
__device__ float g_sa[NBOX];
__device__ float g_sb[DV];
__device__ float g_h[NBOX * DV];

__device__ __forceinline__ float warp_max(float v) {
    v = fmaxf(v, __shfl_xor_sync(0xffffffff, v, 16));
    v = fmaxf(v, __shfl_xor_sync(0xffffffff, v, 8));
    v = fmaxf(v, __shfl_xor_sync(0xffffffff, v, 4));
    v = fmaxf(v, __shfl_xor_sync(0xffffffff, v, 2));
    v = fmaxf(v, __shfl_xor_sync(0xffffffff, v, 1));
    return v;
}

__device__ __forceinline__ int q8(float x, float inv) {
    int q = __float2int_rn(x * inv);
    return max(-127, min(127, q));
}

__device__ __forceinline__ void cpa16(uint32_t dst, const void* src) {
    asm volatile("cp.async.cg.shared.global [%0], [%1], 16;" :: "r"(dst), "l"(src));
}

// ---------------------------------------------------------------------------
// Kernel A: blocks [0,512): ROI max pool -> 2-level int8 quant (per-row scale)
//           blocks [512,1024): W_ff rows -> 2-level int8 quant (2 rows/block)
// (R10 measured-best structure, verbatim.)
// ---------------------------------------------------------------------------
__global__ __launch_bounds__(256) void pre_kernel(
    const float* __restrict__ x, const float* __restrict__ boxes,
    const float* __restrict__ W)
{
    __shared__ float smx[8];
    const int tid  = threadIdx.x;
    const int lane = tid & 31;
    const int wrp  = tid >> 5;

    if (blockIdx.x >= NBOX) {
        const int wb    = blockIdx.x - NBOX;
        const int rhalf = tid >> 7;
        const int row_g = wb * 2 + rhalf;
        const int li    = tid & 127;
        const float* wr = W + (size_t)row_g * DV + li * 8;
        float4 v0 = *(const float4*)(wr);
        float4 v1 = *(const float4*)(wr + 4);
        float v[8] = {v0.x, v0.y, v0.z, v0.w, v1.x, v1.y, v1.z, v1.w};

        float am = 0.f;
        #pragma unroll
        for (int i = 0; i < 8; ++i) am = fmaxf(am, fabsf(v[i]));
        am = warp_max(am);
        if (lane == 0) smx[wrp] = am;
        __syncthreads();
        const int b0 = rhalf * 4;
        float rowmax = fmaxf(fmaxf(smx[b0], smx[b0 + 1]),
                             fmaxf(smx[b0 + 2], smx[b0 + 3]));
        float sa   = rowmax > 0.f ? rowmax * (1.f / 127.f) : 1.f;
        float inv1 = 1.f / sa;
        float inv2 = 254.f / sa;

        uint32_t p1[2] = {0, 0}, p2[2] = {0, 0};
        #pragma unroll
        for (int i = 0; i < 8; ++i) {
            int a = q8(v[i], inv1);
            float r = v[i] - (float)a * sa;
            int b = q8(r, inv2);
            p1[i >> 2] |= ((uint32_t)a & 0xFF) << ((i & 3) * 8);
            p2[i >> 2] |= ((uint32_t)b & 0xFF) << ((i & 3) * 8);
        }
        uint32_t* d1 = g_bq1 + ((size_t)row_g * DV + li * 8) / 4;
        uint32_t* d2 = g_bq2 + ((size_t)row_g * DV + li * 8) / 4;
        d1[0] = p1[0]; d1[1] = p1[1];
        d2[0] = p2[0]; d2[1] = p2[1];
        if (li == 0) g_sb[row_g] = sa;
        return;
    }

    const int n = blockIdx.x;
    const float SC = 14.0f / 224.0f;
    float b0f = boxes[n * 5 + 0];
    float fx1 = boxes[n * 5 + 1];
    float fy1 = boxes[n * 5 + 2];
    float fx2 = boxes[n * 5 + 3];
    float fy2 = boxes[n * 5 + 4];
    int bidx = (int)b0f;
    int cx1 = (int)floorf(fx1 * SC + 0.5f);
    int cy1 = (int)floorf(fy1 * SC + 0.5f);
    int cx2 = (int)floorf(fx2 * SC + 0.5f);
    int cy2 = (int)floorf(fy2 * SC + 0.5f);

    int hs = min(max(cy1, 0), GRID_);
    int he = min(max(max(cy2 + 1, cy1 + 1), 0), GRID_);
    int ws = min(max(cx1, 0), GRID_);
    int we = min(max(max(cx2 + 1, cx1 + 1), 0), GRID_);

    float4 mx = make_float4(0.f, 0.f, 0.f, 0.f);
    if (hs < he && ws < we) {
        const float4* xb = (const float4*)(x + (size_t)bidx * NT * DV);
        mx = make_float4(-INFINITY, -INFINITY, -INFINITY, -INFINITY);
        for (int h = hs; h < he; h += 2) {
            int h1 = min(h + 1, he - 1);
            const float4* r0 = xb + (h  * GRID_) * (DV / 4) + tid;
            const float4* r1 = xb + (h1 * GRID_) * (DV / 4) + tid;
            for (int w = ws; w < we; w += 2) {
                int w1 = min(w + 1, we - 1);
                float4 a = r0[w  * (DV / 4)];
                float4 b = r0[w1 * (DV / 4)];
                float4 c = r1[w  * (DV / 4)];
                float4 d = r1[w1 * (DV / 4)];
                mx.x = fmaxf(fmaxf(fmaxf(mx.x, a.x), fmaxf(b.x, c.x)), d.x);
                mx.y = fmaxf(fmaxf(fmaxf(mx.y, a.y), fmaxf(b.y, c.y)), d.y);
                mx.z = fmaxf(fmaxf(fmaxf(mx.z, a.z), fmaxf(b.z, c.z)), d.z);
                mx.w = fmaxf(fmaxf(fmaxf(mx.w, a.w), fmaxf(b.w, c.w)), d.w);
            }
        }
    }

    float v[4] = {mx.x, mx.y, mx.z, mx.w};
    float am = fmaxf(fmaxf(fabsf(v[0]), fabsf(v[1])),
                     fmaxf(fabsf(v[2]), fabsf(v[3])));
    am = warp_max(am);
    if (lane == 0) smx[wrp] = am;
    __syncthreads();
    float rowmax = 0.f;
    #pragma unroll
    for (int i = 0; i < 8; ++i) rowmax = fmaxf(rowmax, smx[i]);
    float sa   = rowmax > 0.f ? rowmax * (1.f / 127.f) : 1.f;
    float inv1 = 1.f / sa;
    float inv2 = 254.f / sa;

    uint32_t p1 = 0, p2 = 0;
    #pragma unroll
    for (int i = 0; i < 4; ++i) {
        int a = q8(v[i], inv1);
        float r = v[i] - (float)a * sa;
        int b = q8(r, inv2);
        p1 |= ((uint32_t)a & 0xFF) << (i * 8);
        p2 |= ((uint32_t)b & 0xFF) << (i * 8);
    }
    g_aq1[((size_t)n * DV) / 4 + tid] = p1;
    g_aq2[((size_t)n * DV) / 4 + tid] = p2;
    if (tid == 0) g_sa[n] = sa;
}

// ---------------------------------------------------------------------------
// Kernel B: h = pooled @ W^T + bias via int8 mma m16n8k32, 3-term split:
//   C1 = q1a*q1b, C2 = q2a*q1b, C3 = q1a*q2b (exact s32 accum)
//   h  = sa*sb*(C1 + (C2+C3)/254) + bias
// 64x64x32 tiles, 256 threads. 3-stage cp.async ring, ONE __syncthreads/iter:
// reissue targets stage (s+2)%3, consumed LAST iter, protected by this iter's
// top barrier. wait_group 1 + commit-every-iter keeps 1 group pending.
// ---------------------------------------------------------------------------
__device__ __forceinline__ void ldsm4(uint32_t r[4], uint32_t addr) {
    asm volatile("ldmatrix.sync.aligned.m8n8.x4.shared.b16 {%0,%1,%2,%3}, [%4];"
                 : "=r"(r[0]), "=r"(r[1]), "=r"(r[2]), "=r"(r[3]) : "r"(addr));
}

__device__ __forceinline__ void mma_s8(int c[4], const uint32_t a[4],
                                       uint32_t b0, uint32_t b1) {
    asm volatile(
        "mma.sync.aligned.m16n8k32.row.col.s32.s8.s8.s32 "
        "{%0,%1,%2,%3}, {%4,%5,%6,%7}, {%8,%9}, {%0,%1,%2,%3};\n"
        : "+r"(c[0]), "+r"(c[1]), "+r"(c[2]), "+r"(c[3])
        : "r"(a[0]), "r"(a[1]), "r"(a[2]), "r"(a[3]), "r"(b0), "r"(b1));
}

__global__ __launch_bounds__(256) void gemm_s8_kernel(const float* __restrict__ bias)
{
    // S[stage][arr 0=Aq1,1=Aq2,2=Bq1,3=Bq2][row 0..63][48 bytes]
    __shared__ __align__(16) int8_t S[3][4][64][48];

    const int tid  = threadIdx.x;
    const int lane = tid & 31;
    const int wid  = tid >> 5;
    const int wm   = (wid & 1) * 32;
    const int wn   = (wid >> 1) * 16;
    const int bm64 = blockIdx.y * 64;
    const int bn64 = blockIdx.x * 64;

    // cp.async task split: each thread loads one A-array chunk + one B-array chunk
    const int arr_a = tid >> 7;           // 0 -> q1 arrays, 1 -> q2 arrays
    const int rowi  = (tid & 127) >> 1;   // 0..63
    const int offi  = (tid & 1) << 4;     // 0 or 16
    const int8_t* srcA = (const int8_t*)(arr_a ? g_aq2 : g_aq1)
                       + (size_t)(bm64 + rowi) * DV + offi;
    const int8_t* srcB = (const int8_t*)(arr_a ? g_bq2 : g_bq1)
                       + (size_t)(bn64 + rowi) * DV + offi;

    #define ISSUE(ST, K0)                                                      \
    {                                                                          \
        cpa16((uint32_t)__cvta_generic_to_shared(&S[ST][arr_a][rowi][offi]),   \
              srcA + (K0));                                                    \
        cpa16((uint32_t)__cvta_generic_to_shared(&S[ST][2 + arr_a][rowi][offi]),\
              srcB + (K0));                                                    \
    }

    const int arow = lane & 15;
    const int aoff = (lane >> 4) * 16;
    const int brow = (lane & 7) + ((lane >> 4) << 3);
    const int boff = ((lane >> 3) & 1) * 16;

    int c1[2][2][4] = {}, c2[2][2][4] = {}, c3[2][2][4] = {};

    ISSUE(0, 0);
    asm volatile("cp.async.commit_group;");
    ISSUE(1, 32);
    asm volatile("cp.async.commit_group;");

    int s = 0;
    for (int it = 0; it < DV / 32; ++it) {
        asm volatile("cp.async.wait_group 1;");
        __syncthreads();

        uint32_t a1[2][4], a2[2][4], b1[4], b2[4];
        #pragma unroll
        for (int ms = 0; ms < 2; ++ms) {
            ldsm4(a1[ms], (uint32_t)__cvta_generic_to_shared(
                      &S[s][0][wm + ms * 16 + arow][aoff]));
            ldsm4(a2[ms], (uint32_t)__cvta_generic_to_shared(
                      &S[s][1][wm + ms * 16 + arow][aoff]));
        }
        ldsm4(b1, (uint32_t)__cvta_generic_to_shared(&S[s][2][wn + brow][boff]));
        ldsm4(b2, (uint32_t)__cvta_generic_to_shared(&S[s][3][wn + brow][boff]));

        #pragma unroll
        for (int ms = 0; ms < 2; ++ms) {
            #pragma unroll
            for (int nn = 0; nn < 2; ++nn) {
                mma_s8(c1[ms][nn], a1[ms], b1[nn * 2], b1[nn * 2 + 1]);
                mma_s8(c2[ms][nn], a2[ms], b1[nn * 2], b1[nn * 2 + 1]);
                mma_s8(c3[ms][nn], a1[ms], b2[nn * 2], b2[nn * 2 + 1]);
            }
        }

        // reissue into stage consumed LAST iteration (all warps are past this
        // iteration's barrier, hence past last iteration's reads)
        const int nx = it + 2;
        if (nx < DV / 32) {
            const int ps = (s + 2 >= 3) ? (s - 1) : (s + 2);
            ISSUE(ps, nx * 32);
        }
        asm volatile("cp.async.commit_group;");
        s = (s + 1 == 3) ? 0 : s + 1;
    }
    #undef ISSUE

    const int g   = lane >> 2;
    const int tig = lane & 3;
    #pragma unroll
    for (int ms = 0; ms < 2; ++ms) {
        const int m0 = bm64 + wm + ms * 16 + g;
        const float sA0 = g_sa[m0];
        const float sA1 = g_sa[m0 + 8];
        #pragma unroll
        for (int nn = 0; nn < 2; ++nn) {
            const int n0 = bn64 + wn + nn * 8 + tig * 2;
            const float sB0 = g_sb[n0];
            const float sB1 = g_sb[n0 + 1];
            float2 bv = *(const float2*)(bias + n0);
            float t0 = (float)c1[ms][nn][0] +
                       ((float)c2[ms][nn][0] + (float)c3[ms][nn][0]) * INV254;
            float t1 = (float)c1[ms][nn][1] +
                       ((float)c2[ms][nn][1] + (float)c3[ms][nn][1]) * INV254;
            float t2 = (float)c1[ms][nn][2] +
                       ((float)c2[ms][nn][2] + (float)c3[ms][nn][2]) * INV254;
            float t3 = (float)c1[ms][nn][3] +
                       ((float)c2[ms][nn][3] + (float)c3[ms][nn][3]) * INV254;
            float2 r0, r1;
            r0.x = sA0 * sB0 * t0 + bv.x;
            r0.y = sA0 * sB1 * t1 + bv.y;
            r1.x = sA1 * sB0 * t2 + bv.x;
            r1.y = sA1 * sB1 * t3 + bv.y;
            *(float2*)(g_h + (size_t)m0 * DV + n0)       = r0;
            *(float2*)(g_h + (size_t)(m0 + 8) * DV + n0) = r1;
        }
    }
}

// ---------------------------------------------------------------------------
// Kernel C: LayerNorm + exact GELU + heads. One block (256 thr) per box row.
// ---------------------------------------------------------------------------
__device__ __forceinline__ float warp_sum(float v) {
    v += __shfl_xor_sync(0xffffffff, v, 16);
    v += __shfl_xor_sync(0xffffffff, v, 8);
    v += __shfl_xor_sync(0xffffffff, v, 4);
    v += __shfl_xor_sync(0xffffffff, v, 2);
    v += __shfl_xor_sync(0xffffffff, v, 1);
    return v;
}

__global__ __launch_bounds__(256) void epilogue_kernel(
    const float* __restrict__ ln_g, const float* __restrict__ ln_b,
    const int*   __restrict__ labels,
    const float* __restrict__ Wh, const float* __restrict__ bh,
    const float* __restrict__ Wd, const float* __restrict__ bd,
    float* __restrict__ out)
{
    __shared__ float sred[8];
    __shared__ float red10[10][8];

    const int r    = blockIdx.x;
    const int tid  = threadIdx.x;
    const int lane = tid & 31;
    const int wid  = tid >> 5;
    const int d    = tid * 4;

    float4 hv = *(const float4*)(g_h + (size_t)r * DV + d);

    float s = warp_sum(hv.x + hv.y + hv.z + hv.w);
    if (lane == 0) sred[wid] = s;
    __syncthreads();
    float tot = 0.f;
    #pragma unroll
    for (int i = 0; i < 8; ++i) tot += sred[i];
    const float mu = tot * (1.0f / DV);
    __syncthreads();

    float cx = hv.x - mu, cy = hv.y - mu, cz = hv.z - mu, cw = hv.w - mu;
    float s2 = warp_sum(cx * cx + cy * cy + cz * cz + cw * cw);
    if (lane == 0) sred[wid] = s2;
    __syncthreads();
    float tot2 = 0.f;
    #pragma unroll
    for (int i = 0; i < 8; ++i) tot2 += sred[i];
    const float rstd = rsqrtf(tot2 * (1.0f / DV) + 1e-5f);

    float4 g4 = *(const float4*)(ln_g + d);
    float4 b4 = *(const float4*)(ln_b + d);
    float4 y4;
    y4.x = cx * rstd * g4.x + b4.x;
    y4.y = cy * rstd * g4.y + b4.y;
    y4.z = cz * rstd * g4.z + b4.z;
    y4.w = cw * rstd * g4.w + b4.w;

    const float IS2 = 0.70710678118654752f;
    y4.x = y4.x * 0.5f * (1.0f + erff(y4.x * IS2));
    y4.y = y4.y * 0.5f * (1.0f + erff(y4.y * IS2));
    y4.z = y4.z * 0.5f * (1.0f + erff(y4.z * IS2));
    y4.w = y4.w * 0.5f * (1.0f + erff(y4.w * IS2));

    *(float4*)(out + Y_OFF + (size_t)r * DV + d) = y4;

    const int lab  = labels[r];
    const int ncat = c_id2cat[lab];
    const float* whp = Wh + (size_t)lab * MAXATT * DV;

    float p[10];
    #pragma unroll
    for (int k = 0; k < MAXATT; ++k) {
        if (k < ncat) {
            float4 w4 = *(const float4*)(whp + (size_t)k * DV + d);
            p[k] = y4.x * w4.x + y4.y * w4.y + y4.z * w4.z + y4.w * w4.w;
        } else {
            p[k] = 0.0f;
        }
    }
    {
        float4 w4 = *(const float4*)(Wd + d);
        p[9] = y4.x * w4.x + y4.y * w4.y + y4.z * w4.z + y4.w * w4.w;
    }

    __syncthreads();
    #pragma unroll
    for (int i = 0; i < 10; ++i) {
        float v = warp_sum(p[i]);
        if (lane == 0) red10[i][wid] = v;
    }
    __syncthreads();

    if (tid < 10) {
        float t2 = 0.f;
        #pragma unroll
        for (int i = 0; i < 8; ++i) t2 += red10[tid][i];
        if (tid < MAXATT) {
            float lv = (tid < ncat) ? (t2 + bh[lab * MAXATT + tid]) : 0.0f;
            out[L_OFF + r * MAXATT + tid] = lv;
        } else {
            out[D_OFF + r] = t2 + bd[0];
        }
    }
}

// ---------------------------------------------------------------------------
extern "C" void kernel_launch(void* const* d_in, const int* in_sizes, int n_in,
                              void* d_out, int out_size)
{
    const float* x      = (const float*)d_in[0];
    const float* boxes  = (const float*)d_in[1];
    const int*   labels = (const int*)  d_in[2];
    const float* W_ff   = (const float*)d_in[3];
    const float* b_ff   = (const float*)d_in[4];
    const float* ln_g   = (const float*)d_in[5];
    const float* ln_b   = (const float*)d_in[6];
    const float* Wh     = (const float*)d_in[7];
    const float* bh     = (const float*)d_in[8];
    const float* Wd     = (const float*)d_in[9];
    const float* bd     = (const float*)d_in[10];
    float* out = (float*)d_out;

    pre_kernel<<<NBOX + 512, 256>>>(x, boxes, W_ff);

    dim3 gg(DV / 64, NBOX / 64);   // 16 x 8 = 128 blocks
    gemm_s8_kernel<<<gg, 256>>>(b_ff);

    epilogue_kernel<<<NBOX, 256>>>(ln_g, ln_b, labels, Wh, bh, Wd, bd, out);
}

// round 17
// speedup vs baseline: 1.0857x; 1.0024x over previous
#include <cuda_runtime.h>
#include <cuda_bf16.h>
#include <math.h>
#include <stdint.h>

#define BSZ   32
#define NT    196
#define DV    1024
#define NBOX  512
#define GRID_ 14
#define MAXATT 9
#define NLAB  20

#define Y_OFF   0
#define L_OFF   (NBOX * DV)              // 524288
#define D_OFF   (L_OFF + NBOX * MAXATT)  // 528896

#define INV254 (1.0f / 254.0f)

__constant__ int c_id2cat[NLAB] = {3,5,2,4,6,3,7,2,5,4,8,3,2,6,5,4,3,9,2,5};

// A and B both 2-level int8 (q1 + q2/254), per-row scales.
__device__ __align__(16) uint32_t g_aq1[NBOX * DV / 4];
__device__ __align__(16) uint32_t g_aq2[NBOX * DV / 4];
__device__ __align__(16) uint32_t g_bq1[DV * DV / 4];
__device__ __align__(16) uint32_t g_bq2[DV * DV / 4];
__device__ float g_sa[NBOX];
__device__ float g_sb[DV];
__device__ float g_h[NBOX * DV];

__device__ __forceinline__ float warp_max(float v) {
    v = fmaxf(v, __shfl_xor_sync(0xffffffff, v, 16));
    v = fmaxf(v, __shfl_xor_sync(0xffffffff, v, 8));
    v = fmaxf(v, __shfl_xor_sync(0xffffffff, v, 4));
    v = fmaxf(v, __shfl_xor_sync(0xffffffff, v, 2));
    v = fmaxf(v, __shfl_xor_sync(0xffffffff, v, 1));
    return v;
}

__device__ __forceinline__ int q8(float x, float inv) {
    int q = __float2int_rn(x * inv);
    return max(-127, min(127, q));
}

__device__ __forceinline__ void cpa16(uint32_t dst, const void* src) {
    asm volatile("cp.async.cg.shared.global [%0], [%1], 16;" :: "r"(dst), "l"(src));
}

// ---------------------------------------------------------------------------
// Kernel A: blocks [0,512): ROI max pool -> 2-level int8 quant (per-row scale)
//           blocks [512,1024): W_ff rows -> 2-level int8 quant (2 rows/block)
// (R10 measured-best structure, verbatim.)
// ---------------------------------------------------------------------------
__global__ __launch_bounds__(256) void pre_kernel(
    const float* __restrict__ x, const float* __restrict__ boxes,
    const float* __restrict__ W)
{
    __shared__ float smx[8];
    const int tid  = threadIdx.x;
    const int lane = tid & 31;
    const int wrp  = tid >> 5;

    if (blockIdx.x >= NBOX) {
        const int wb    = blockIdx.x - NBOX;
        const int rhalf = tid >> 7;
        const int row_g = wb * 2 + rhalf;
        const int li    = tid & 127;
        const float* wr = W + (size_t)row_g * DV + li * 8;
        float4 v0 = *(const float4*)(wr);
        float4 v1 = *(const float4*)(wr + 4);
        float v[8] = {v0.x, v0.y, v0.z, v0.w, v1.x, v1.y, v1.z, v1.w};

        float am = 0.f;
        #pragma unroll
        for (int i = 0; i < 8; ++i) am = fmaxf(am, fabsf(v[i]));
        am = warp_max(am);
        if (lane == 0) smx[wrp] = am;
        __syncthreads();
        const int b0 = rhalf * 4;
        float rowmax = fmaxf(fmaxf(smx[b0], smx[b0 + 1]),
                             fmaxf(smx[b0 + 2], smx[b0 + 3]));
        float sa   = rowmax > 0.f ? rowmax * (1.f / 127.f) : 1.f;
        float inv1 = 1.f / sa;
        float inv2 = 254.f / sa;

        uint32_t p1[2] = {0, 0}, p2[2] = {0, 0};
        #pragma unroll
        for (int i = 0; i < 8; ++i) {
            int a = q8(v[i], inv1);
            float r = v[i] - (float)a * sa;
            int b = q8(r, inv2);
            p1[i >> 2] |= ((uint32_t)a & 0xFF) << ((i & 3) * 8);
            p2[i >> 2] |= ((uint32_t)b & 0xFF) << ((i & 3) * 8);
        }
        uint32_t* d1 = g_bq1 + ((size_t)row_g * DV + li * 8) / 4;
        uint32_t* d2 = g_bq2 + ((size_t)row_g * DV + li * 8) / 4;
        d1[0] = p1[0]; d1[1] = p1[1];
        d2[0] = p2[0]; d2[1] = p2[1];
        if (li == 0) g_sb[row_g] = sa;
        return;
    }

    const int n = blockIdx.x;
    const float SC = 14.0f / 224.0f;
    float b0f = boxes[n * 5 + 0];
    float fx1 = boxes[n * 5 + 1];
    float fy1 = boxes[n * 5 + 2];
    float fx2 = boxes[n * 5 + 3];
    float fy2 = boxes[n * 5 + 4];
    int bidx = (int)b0f;
    int cx1 = (int)floorf(fx1 * SC + 0.5f);
    int cy1 = (int)floorf(fy1 * SC + 0.5f);
    int cx2 = (int)floorf(fx2 * SC + 0.5f);
    int cy2 = (int)floorf(fy2 * SC + 0.5f);

    int hs = min(max(cy1, 0), GRID_);
    int he = min(max(max(cy2 + 1, cy1 + 1), 0), GRID_);
    int ws = min(max(cx1, 0), GRID_);
    int we = min(max(max(cx2 + 1, cx1 + 1), 0), GRID_);

    float4 mx = make_float4(0.f, 0.f, 0.f, 0.f);
    if (hs < he && ws < we) {
        const float4* xb = (const float4*)(x + (size_t)bidx * NT * DV);
        mx = make_float4(-INFINITY, -INFINITY, -INFINITY, -INFINITY);
        for (int h = hs; h < he; h += 2) {
            int h1 = min(h + 1, he - 1);
            const float4* r0 = xb + (h  * GRID_) * (DV / 4) + tid;
            const float4* r1 = xb + (h1 * GRID_) * (DV / 4) + tid;
            for (int w = ws; w < we; w += 2) {
                int w1 = min(w + 1, we - 1);
                float4 a = r0[w  * (DV / 4)];
                float4 b = r0[w1 * (DV / 4)];
                float4 c = r1[w  * (DV / 4)];
                float4 d = r1[w1 * (DV / 4)];
                mx.x = fmaxf(fmaxf(fmaxf(mx.x, a.x), fmaxf(b.x, c.x)), d.x);
                mx.y = fmaxf(fmaxf(fmaxf(mx.y, a.y), fmaxf(b.y, c.y)), d.y);
                mx.z = fmaxf(fmaxf(fmaxf(mx.z, a.z), fmaxf(b.z, c.z)), d.z);
                mx.w = fmaxf(fmaxf(fmaxf(mx.w, a.w), fmaxf(b.w, c.w)), d.w);
            }
        }
    }

    float v[4] = {mx.x, mx.y, mx.z, mx.w};
    float am = fmaxf(fmaxf(fabsf(v[0]), fabsf(v[1])),
                     fmaxf(fabsf(v[2]), fabsf(v[3])));
    am = warp_max(am);
    if (lane == 0) smx[wrp] = am;
    __syncthreads();
    float rowmax = 0.f;
    #pragma unroll
    for (int i = 0; i < 8; ++i) rowmax = fmaxf(rowmax, smx[i]);
    float sa   = rowmax > 0.f ? rowmax * (1.f / 127.f) : 1.f;
    float inv1 = 1.f / sa;
    float inv2 = 254.f / sa;

    uint32_t p1 = 0, p2 = 0;
    #pragma unroll
    for (int i = 0; i < 4; ++i) {
        int a = q8(v[i], inv1);
        float r = v[i] - (float)a * sa;
        int b = q8(r, inv2);
        p1 |= ((uint32_t)a & 0xFF) << (i * 8);
        p2 |= ((uint32_t)b & 0xFF) << (i * 8);
    }
    g_aq1[((size_t)n * DV) / 4 + tid] = p1;
    g_aq2[((size_t)n * DV) / 4 + tid] = p2;
    if (tid == 0) g_sa[n] = sa;
}

// ---------------------------------------------------------------------------
// Kernel B: h = pooled @ W^T + bias via int8 mma m16n8k32, 3-term split.
// 64x64x32 tiles, 256 threads. 4-stage cp.async ring, ONE __syncthreads/iter:
// reissue targets stage (s+3)%4, consumed LAST iter, protected by this iter's
// top barrier. wait_group 2 + commit-every-iter keeps pipeline depth 3.
// ---------------------------------------------------------------------------
__device__ __forceinline__ void ldsm4(uint32_t r[4], uint32_t addr) {
    asm volatile("ldmatrix.sync.aligned.m8n8.x4.shared.b16 {%0,%1,%2,%3}, [%4];"
                 : "=r"(r[0]), "=r"(r[1]), "=r"(r[2]), "=r"(r[3]) : "r"(addr));
}

__device__ __forceinline__ void mma_s8(int c[4], const uint32_t a[4],
                                       uint32_t b0, uint32_t b1) {
    asm volatile(
        "mma.sync.aligned.m16n8k32.row.col.s32.s8.s8.s32 "
        "{%0,%1,%2,%3}, {%4,%5,%6,%7}, {%8,%9}, {%0,%1,%2,%3};\n"
        : "+r"(c[0]), "+r"(c[1]), "+r"(c[2]), "+r"(c[3])
        : "r"(a[0]), "r"(a[1]), "r"(a[2]), "r"(a[3]), "r"(b0), "r"(b1));
}

__global__ __launch_bounds__(256) void gemm_s8_kernel(const float* __restrict__ bias)
{
    // S[stage][arr 0=Aq1,1=Aq2,2=Bq1,3=Bq2][row 0..63][48 bytes]  = 48KB
    __shared__ __align__(16) int8_t S[4][4][64][48];

    const int tid  = threadIdx.x;
    const int lane = tid & 31;
    const int wid  = tid >> 5;
    const int wm   = (wid & 1) * 32;
    const int wn   = (wid >> 1) * 16;
    const int bm64 = blockIdx.y * 64;
    const int bn64 = blockIdx.x * 64;

    const int arr_a = tid >> 7;           // 0 -> q1 arrays, 1 -> q2 arrays
    const int rowi  = (tid & 127) >> 1;   // 0..63
    const int offi  = (tid & 1) << 4;     // 0 or 16
    const int8_t* srcA = (const int8_t*)(arr_a ? g_aq2 : g_aq1)
                       + (size_t)(bm64 + rowi) * DV + offi;
    const int8_t* srcB = (const int8_t*)(arr_a ? g_bq2 : g_bq1)
                       + (size_t)(bn64 + rowi) * DV + offi;

    #define ISSUE(ST, K0)                                                      \
    {                                                                          \
        cpa16((uint32_t)__cvta_generic_to_shared(&S[ST][arr_a][rowi][offi]),   \
              srcA + (K0));                                                    \
        cpa16((uint32_t)__cvta_generic_to_shared(&S[ST][2 + arr_a][rowi][offi]),\
              srcB + (K0));                                                    \
    }

    const int arow = lane & 15;
    const int aoff = (lane >> 4) * 16;
    const int brow = (lane & 7) + ((lane >> 4) << 3);
    const int boff = ((lane >> 3) & 1) * 16;

    int c1[2][2][4] = {}, c2[2][2][4] = {}, c3[2][2][4] = {};

    ISSUE(0, 0);
    asm volatile("cp.async.commit_group;");
    ISSUE(1, 32);
    asm volatile("cp.async.commit_group;");
    ISSUE(2, 64);
    asm volatile("cp.async.commit_group;");

    int s = 0;
    for (int it = 0; it < DV / 32; ++it) {
        asm volatile("cp.async.wait_group 2;");
        __syncthreads();

        uint32_t a1[2][4], a2[2][4], b1[4], b2[4];
        #pragma unroll
        for (int ms = 0; ms < 2; ++ms) {
            ldsm4(a1[ms], (uint32_t)__cvta_generic_to_shared(
                      &S[s][0][wm + ms * 16 + arow][aoff]));
            ldsm4(a2[ms], (uint32_t)__cvta_generic_to_shared(
                      &S[s][1][wm + ms * 16 + arow][aoff]));
        }
        ldsm4(b1, (uint32_t)__cvta_generic_to_shared(&S[s][2][wn + brow][boff]));
        ldsm4(b2, (uint32_t)__cvta_generic_to_shared(&S[s][3][wn + brow][boff]));

        #pragma unroll
        for (int ms = 0; ms < 2; ++ms) {
            #pragma unroll
            for (int nn = 0; nn < 2; ++nn) {
                mma_s8(c1[ms][nn], a1[ms], b1[nn * 2], b1[nn * 2 + 1]);
                mma_s8(c2[ms][nn], a2[ms], b1[nn * 2], b1[nn * 2 + 1]);
                mma_s8(c3[ms][nn], a1[ms], b2[nn * 2], b2[nn * 2 + 1]);
            }
        }

        // reissue into stage consumed LAST iteration
        const int nx = it + 3;
        if (nx < DV / 32) {
            const int ps = (s + 3 >= 4) ? (s - 1) : (s + 3);
            ISSUE(ps, nx * 32);
        }
        asm volatile("cp.async.commit_group;");
        s = (s + 1 == 4) ? 0 : s + 1;
    }
    #undef ISSUE

    const int g   = lane >> 2;
    const int tig = lane & 3;
    #pragma unroll
    for (int ms = 0; ms < 2; ++ms) {
        const int m0 = bm64 + wm + ms * 16 + g;
        const float sA0 = g_sa[m0];
        const float sA1 = g_sa[m0 + 8];
        #pragma unroll
        for (int nn = 0; nn < 2; ++nn) {
            const int n0 = bn64 + wn + nn * 8 + tig * 2;
            const float sB0 = g_sb[n0];
            const float sB1 = g_sb[n0 + 1];
            float2 bv = *(const float2*)(bias + n0);
            float t0 = (float)c1[ms][nn][0] +
                       ((float)c2[ms][nn][0] + (float)c3[ms][nn][0]) * INV254;
            float t1 = (float)c1[ms][nn][1] +
                       ((float)c2[ms][nn][1] + (float)c3[ms][nn][1]) * INV254;
            float t2 = (float)c1[ms][nn][2] +
                       ((float)c2[ms][nn][2] + (float)c3[ms][nn][2]) * INV254;
            float t3 = (float)c1[ms][nn][3] +
                       ((float)c2[ms][nn][3] + (float)c3[ms][nn][3]) * INV254;
            float2 r0, r1;
            r0.x = sA0 * sB0 * t0 + bv.x;
            r0.y = sA0 * sB1 * t1 + bv.y;
            r1.x = sA1 * sB0 * t2 + bv.x;
            r1.y = sA1 * sB1 * t3 + bv.y;
            *(float2*)(g_h + (size_t)m0 * DV + n0)       = r0;
            *(float2*)(g_h + (size_t)(m0 + 8) * DV + n0) = r1;
        }
    }
}

// ---------------------------------------------------------------------------
// Kernel C: LayerNorm + exact GELU + heads.
// 2 rows per block: 256 blocks x 256 thr; threads [0,128) row A, [128,256)
// row B; 8 elems/thread; 4-warp reductions per row.
// ---------------------------------------------------------------------------
__device__ __forceinline__ float warp_sum(float v) {
    v += __shfl_xor_sync(0xffffffff, v, 16);
    v += __shfl_xor_sync(0xffffffff, v, 8);
    v += __shfl_xor_sync(0xffffffff, v, 4);
    v += __shfl_xor_sync(0xffffffff, v, 2);
    v += __shfl_xor_sync(0xffffffff, v, 1);
    return v;
}

__global__ __launch_bounds__(256) void epilogue_kernel(
    const float* __restrict__ ln_g, const float* __restrict__ ln_b,
    const int*   __restrict__ labels,
    const float* __restrict__ Wh, const float* __restrict__ bh,
    const float* __restrict__ Wd, const float* __restrict__ bd,
    float* __restrict__ out)
{
    __shared__ float smx[8];
    __shared__ float red[8][10];

    const int tid   = threadIdx.x;
    const int lane  = tid & 31;
    const int wrp   = tid >> 5;          // 0..7
    const int rhalf = tid >> 7;          // 0 or 1
    const int li    = tid & 127;
    const int r     = blockIdx.x * 2 + rhalf;
    const int d     = li * 8;

    const float* hrow = g_h + (size_t)r * DV + d;
    float4 h0 = *(const float4*)(hrow);
    float4 h1 = *(const float4*)(hrow + 4);
    float hv[8] = {h0.x, h0.y, h0.z, h0.w, h1.x, h1.y, h1.z, h1.w};

    // mean (4-warp reduction per row)
    float sacc = 0.f;
    #pragma unroll
    for (int i = 0; i < 8; ++i) sacc += hv[i];
    sacc = warp_sum(sacc);
    if (lane == 0) smx[wrp] = sacc;
    __syncthreads();
    const int w0 = rhalf * 4;
    float tot = smx[w0] + smx[w0 + 1] + smx[w0 + 2] + smx[w0 + 3];
    const float mu = tot * (1.0f / DV);
    __syncthreads();

    // variance
    float cv[8];
    float s2 = 0.f;
    #pragma unroll
    for (int i = 0; i < 8; ++i) { cv[i] = hv[i] - mu; s2 += cv[i] * cv[i]; }
    s2 = warp_sum(s2);
    if (lane == 0) smx[wrp] = s2;
    __syncthreads();
    float tot2 = smx[w0] + smx[w0 + 1] + smx[w0 + 2] + smx[w0 + 3];
    const float rstd = rsqrtf(tot2 * (1.0f / DV) + 1e-5f);

    // LN + exact GELU
    float4 g0 = *(const float4*)(ln_g + d);
    float4 g1 = *(const float4*)(ln_g + d + 4);
    float4 b0 = *(const float4*)(ln_b + d);
    float4 b1 = *(const float4*)(ln_b + d + 4);
    float gv[8] = {g0.x, g0.y, g0.z, g0.w, g1.x, g1.y, g1.z, g1.w};
    float bv[8] = {b0.x, b0.y, b0.z, b0.w, b1.x, b1.y, b1.z, b1.w};
    const float IS2 = 0.70710678118654752f;
    float yv[8];
    #pragma unroll
    for (int i = 0; i < 8; ++i) {
        float y = cv[i] * rstd * gv[i] + bv[i];
        yv[i] = y * 0.5f * (1.0f + erff(y * IS2));
    }
    float4 o0 = make_float4(yv[0], yv[1], yv[2], yv[3]);
    float4 o1 = make_float4(yv[4], yv[5], yv[6], yv[7]);
    *(float4*)(out + Y_OFF + (size_t)r * DV + d)     = o0;
    *(float4*)(out + Y_OFF + (size_t)r * DV + d + 4) = o1;

    // heads
    const int lab  = labels[r];
    const int ncat = c_id2cat[lab];
    const float* whp = Wh + (size_t)lab * MAXATT * DV;

    float p[10];
    #pragma unroll
    for (int k = 0; k < MAXATT; ++k) {
        if (k < ncat) {
            const float* wr = whp + (size_t)k * DV + d;
            float4 w0 = *(const float4*)(wr);
            float4 w1 = *(const float4*)(wr + 4);
            p[k] = yv[0]*w0.x + yv[1]*w0.y + yv[2]*w0.z + yv[3]*w0.w
                 + yv[4]*w1.x + yv[5]*w1.y + yv[6]*w1.z + yv[7]*w1.w;
        } else {
            p[k] = 0.0f;
        }
    }
    {
        const float* wr = Wd + d;
        float4 w0 = *(const float4*)(wr);
        float4 w1 = *(const float4*)(wr + 4);
        p[9] = yv[0]*w0.x + yv[1]*w0.y + yv[2]*w0.z + yv[3]*w0.w
             + yv[4]*w1.x + yv[5]*w1.y + yv[6]*w1.z + yv[7]*w1.w;
    }

    __syncthreads();   // protect smx/red reuse ordering
    #pragma unroll
    for (int i = 0; i < 10; ++i) {
        float v = warp_sum(p[i]);
        if (lane == 0) red[wrp][i] = v;
    }
    __syncthreads();

    if (li < 10) {
        float t2 = red[w0][li] + red[w0 + 1][li] + red[w0 + 2][li] + red[w0 + 3][li];
        if (li < MAXATT) {
            float lv = (li < ncat) ? (t2 + bh[lab * MAXATT + li]) : 0.0f;
            out[L_OFF + r * MAXATT + li] = lv;
        } else {
            out[D_OFF + r] = t2 + bd[0];
        }
    }
}

// ---------------------------------------------------------------------------
extern "C" void kernel_launch(void* const* d_in, const int* in_sizes, int n_in,
                              void* d_out, int out_size)
{
    const float* x      = (const float*)d_in[0];
    const float* boxes  = (const float*)d_in[1];
    const int*   labels = (const int*)  d_in[2];
    const float* W_ff   = (const float*)d_in[3];
    const float* b_ff   = (const float*)d_in[4];
    const float* ln_g   = (const float*)d_in[5];
    const float* ln_b   = (const float*)d_in[6];
    const float* Wh     = (const float*)d_in[7];
    const float* bh     = (const float*)d_in[8];
    const float* Wd     = (const float*)d_in[9];
    const float* bd     = (const float*)d_in[10];
    float* out = (float*)d_out;

    pre_kernel<<<NBOX + 512, 256>>>(x, boxes, W_ff);

    dim3 gg(DV / 64, NBOX / 64);   // 16 x 8 = 128 blocks
    gemm_s8_kernel<<<gg, 256>>>(b_ff);

    epilogue_kernel<<<NBOX / 2, 256>>>(ln_g, ln_b, labels, Wh, bh, Wd, bd, out);
}